// round 4
// baseline (speedup 1.0000x reference)
#include <cuda_runtime.h>

// Lorenz RK4 step, one step of size DT, batched over N=8M states.
// Pure streaming kernel: 12B in + 12B out per state (192 MB total traffic).
// Each thread owns 4 consecutive states = 12 floats = 3x float4 loads/stores.

#define DT     0.01f
#define SIGMA  10.0f
#define RHO    28.0f
#define BETA   (8.0f / 3.0f)

__device__ __forceinline__ void lorenz_f(float x, float y, float z,
                                         float& dx, float& dy, float& dz) {
    dx = SIGMA * (y - x);
    dy = x * (RHO - z) - y;
    dz = x * y - BETA * z;
}

__device__ __forceinline__ void rk4_step(float& x, float& y, float& z) {
    const float h2 = 0.5f * DT;
    float k1x, k1y, k1z, k2x, k2y, k2z, k3x, k3y, k3z, k4x, k4y, k4z;

    lorenz_f(x, y, z, k1x, k1y, k1z);
    lorenz_f(x + h2 * k1x, y + h2 * k1y, z + h2 * k1z, k2x, k2y, k2z);
    lorenz_f(x + h2 * k2x, y + h2 * k2y, z + h2 * k2z, k3x, k3y, k3z);
    lorenz_f(x + DT * k3x, y + DT * k3y, z + DT * k3z, k4x, k4y, k4z);

    const float w = DT / 6.0f;
    x += w * (k1x + 2.0f * k2x + 2.0f * k3x + k4x);
    y += w * (k1y + 2.0f * k2y + 2.0f * k3y + k4y);
    z += w * (k1z + 2.0f * k2z + 2.0f * k3z + k4z);
}

__global__ void __launch_bounds__(256)
lorenz_rk4_kernel(const float4* __restrict__ in4,
                  float4* __restrict__ out4,
                  int n_vec)                 // number of full 4-state groups
{
    int t = blockIdx.x * blockDim.x + threadIdx.x;
    if (t >= n_vec) return;

    int b = 3 * t;
    float4 a = in4[b + 0];
    float4 c = in4[b + 1];
    float4 d = in4[b + 2];

    float s[12] = { a.x, a.y, a.z, a.w,
                    c.x, c.y, c.z, c.w,
                    d.x, d.y, d.z, d.w };
    #pragma unroll
    for (int i = 0; i < 4; i++)
        rk4_step(s[3 * i + 0], s[3 * i + 1], s[3 * i + 2]);

    out4[b + 0] = make_float4(s[0], s[1], s[2],  s[3]);
    out4[b + 1] = make_float4(s[4], s[5], s[6],  s[7]);
    out4[b + 2] = make_float4(s[8], s[9], s[10], s[11]);
}

__global__ void
lorenz_rk4_tail_kernel(const float* __restrict__ in,
                       float* __restrict__ out,
                       int start, int n_states)
{
    int i = start + blockIdx.x * blockDim.x + threadIdx.x;
    if (i >= n_states) return;
    float x = in[3 * i + 0];
    float y = in[3 * i + 1];
    float z = in[3 * i + 2];
    rk4_step(x, y, z);
    out[3 * i + 0] = x;
    out[3 * i + 1] = y;
    out[3 * i + 2] = z;
}

extern "C" void kernel_launch(void* const* d_in, const int* in_sizes, int n_in,
                              void* d_out, int out_size)
{
    const float* in = (const float*)d_in[0];
    float* out = (float*)d_out;
    int n_states = in_sizes[0] / 3;        // 8,000,000

    int n_vec = n_states / 4;              // full 4-state groups (2,000,000)
    int block = 256;
    int grid = (n_vec + block - 1) / block;

    if (n_vec > 0)
        lorenz_rk4_kernel<<<grid, block>>>((const float4*)in, (float4*)out, n_vec);

    int tail = n_states - n_vec * 4;       // 0 for N=8M
    if (tail > 0)
        lorenz_rk4_tail_kernel<<<1, 128>>>(in, out, n_vec * 4, n_states);
}

// round 5
// speedup vs baseline: 1.0214x; 1.0214x over previous
#include <cuda_runtime.h>

// Lorenz RK4 step over N=8M states, pure streaming (192 MB total traffic).
// Smem-staged layout: all global LDG/STG are fully coalesced float4;
// the 12B-stride state access happens in shared memory (conflict-free).

#define DT     0.01f
#define SIGMA  10.0f
#define RHO    28.0f
#define BETA   (8.0f / 3.0f)

#define BLOCK_THREADS   128
#define STATES_PER_THR  4
#define STATES_PER_BLK  (BLOCK_THREADS * STATES_PER_THR)    // 512
#define VEC4_PER_BLK    (STATES_PER_BLK * 3 / 4)            // 384 float4

__device__ __forceinline__ void lorenz_f(float x, float y, float z,
                                         float& dx, float& dy, float& dz) {
    dx = SIGMA * (y - x);
    dy = x * (RHO - z) - y;
    dz = x * y - BETA * z;
}

__device__ __forceinline__ void rk4_step(float& x, float& y, float& z) {
    const float h2 = 0.5f * DT;
    float k1x, k1y, k1z, k2x, k2y, k2z, k3x, k3y, k3z, k4x, k4y, k4z;

    lorenz_f(x, y, z, k1x, k1y, k1z);
    lorenz_f(x + h2 * k1x, y + h2 * k1y, z + h2 * k1z, k2x, k2y, k2z);
    lorenz_f(x + h2 * k2x, y + h2 * k2y, z + h2 * k2z, k3x, k3y, k3z);
    lorenz_f(x + DT * k3x, y + DT * k3y, z + DT * k3z, k4x, k4y, k4z);

    const float w = DT / 6.0f;
    x += w * (k1x + 2.0f * k2x + 2.0f * k3x + k4x);
    y += w * (k1y + 2.0f * k2y + 2.0f * k3y + k4y);
    z += w * (k1z + 2.0f * k2z + 2.0f * k3z + k4z);
}

__global__ void __launch_bounds__(BLOCK_THREADS)
lorenz_rk4_staged_kernel(const float4* __restrict__ in4,
                         float4* __restrict__ out4)
{
    __shared__ float4 tile[VEC4_PER_BLK];            // 6 KB

    const int tid  = threadIdx.x;
    const long long base = (long long)blockIdx.x * VEC4_PER_BLK;

    // Phase 1: fully coalesced global -> smem (3x LDG.128 per thread).
    #pragma unroll
    for (int k = 0; k < 3; k++)
        tile[tid + k * BLOCK_THREADS] = in4[base + tid + k * BLOCK_THREADS];

    __syncthreads();

    // Phase 2: each thread owns 4 consecutive states = 12 contiguous floats
    // in smem (3x LDS.128 at 48B stride: bank-conflict-free).
    float* my = (float*)tile + tid * 12;
    float s[12];
    #pragma unroll
    for (int k = 0; k < 3; k++) {
        float4 v = ((float4*)my)[k];
        s[4*k+0] = v.x; s[4*k+1] = v.y; s[4*k+2] = v.z; s[4*k+3] = v.w;
    }

    #pragma unroll
    for (int i = 0; i < STATES_PER_THR; i++)
        rk4_step(s[3*i + 0], s[3*i + 1], s[3*i + 2]);

    // Write back to own smem slots (no cross-thread hazard).
    #pragma unroll
    for (int k = 0; k < 3; k++)
        ((float4*)my)[k] = make_float4(s[4*k+0], s[4*k+1], s[4*k+2], s[4*k+3]);

    __syncthreads();

    // Phase 3: fully coalesced smem -> global (3x STG.128 per thread).
    #pragma unroll
    for (int k = 0; k < 3; k++)
        out4[base + tid + k * BLOCK_THREADS] = tile[tid + k * BLOCK_THREADS];
}

// Scalar tail for N not divisible by STATES_PER_BLK (unused for N=8M).
__global__ void
lorenz_rk4_tail_kernel(const float* __restrict__ in,
                       float* __restrict__ out,
                       int start, int n_states)
{
    int i = start + blockIdx.x * blockDim.x + threadIdx.x;
    if (i >= n_states) return;
    float x = in[3*i + 0];
    float y = in[3*i + 1];
    float z = in[3*i + 2];
    rk4_step(x, y, z);
    out[3*i + 0] = x;
    out[3*i + 1] = y;
    out[3*i + 2] = z;
}

extern "C" void kernel_launch(void* const* d_in, const int* in_sizes, int n_in,
                              void* d_out, int out_size)
{
    const float* in = (const float*)d_in[0];
    float* out = (float*)d_out;
    int n_states = in_sizes[0] / 3;                   // 8,000,000

    int n_full_blocks = n_states / STATES_PER_BLK;    // 15625 for 8M
    if (n_full_blocks > 0)
        lorenz_rk4_staged_kernel<<<n_full_blocks, BLOCK_THREADS>>>(
            (const float4*)in, (float4*)out);

    int done = n_full_blocks * STATES_PER_BLK;
    int tail = n_states - done;                       // 0 for 8M
    if (tail > 0) {
        int block = 256;
        int grid = (tail + block - 1) / block;
        lorenz_rk4_tail_kernel<<<grid, block>>>(in, out, done, n_states);
    }
}